// round 7
// baseline (speedup 1.0000x reference)
#include <cuda_runtime.h>
#include <cuda_bf16.h>

#define N_NODES 50000
#define N_EDGES 500000
#define N_GRAPHS 100
#define DD 146
#define NS 160          // padded row stride (float): 640B = 5 x 128B lines (R7: was 148)
#define BN_EPS 1e-5f

// ---------------- scratch (static device globals; no allocation) ----------------
__device__ __align__(256) float g_h   [N_NODES * NS];
__device__ __align__(256) float g_hW  [N_NODES * NS];
__device__ __align__(256) float g_agg [N_NODES * NS];
__device__ __align__(256) float g_hacc[N_NODES * NS];
__device__ float g_norm_src[N_NODES];
__device__ float g_norm_dst[N_NODES];
__device__ float g_counts[N_GRAPHS];
__device__ __align__(16) float g_hg[N_GRAPHS * DD];
__device__ float g_bnsum[2 * NS];   // [0:NS) col sums, [NS:2NS) col sumsq
__device__ float g_mean[NS];
__device__ float g_rstd[NS];
// CSR (in-edges grouped by dst)
__device__ int g_row_off[N_NODES + 1];
__device__ int g_cursor[N_NODES];
__device__ int g_edge_src[N_EDGES];

// ---------------- init ----------------
__global__ void zero_init_kernel() {
    int idx = blockIdx.x * blockDim.x + threadIdx.x;
    int stride = gridDim.x * blockDim.x;
    const float4 z4 = make_float4(0.f, 0.f, 0.f, 0.f);
    const int n4 = N_NODES * NS / 4;
    float4* hacc4 = reinterpret_cast<float4*>(g_hacc);
    for (int i = idx; i < n4; i += stride) hacc4[i] = z4;
    for (int i = idx; i < N_NODES; i += stride) { g_norm_src[i] = 0.f; g_norm_dst[i] = 0.f; }
    for (int i = idx; i < N_NODES + 1; i += stride) g_row_off[i] = 0;
    for (int i = idx; i < N_GRAPHS * DD; i += stride) g_hg[i] = 0.f;
    for (int i = idx; i < N_GRAPHS; i += stride) g_counts[i] = 0.f;
    for (int i = idx; i < 2 * NS; i += stride) g_bnsum[i] = 0.f;
}

// ---------------- degrees + CSR histogram ----------------
__global__ void deg_kernel(const int* __restrict__ src, const int* __restrict__ dst) {
    int idx = blockIdx.x * blockDim.x + threadIdx.x;
    int stride = gridDim.x * blockDim.x;
    for (int e = idx; e < N_EDGES; e += stride) {
        int d = dst[e];
        atomicAdd(&g_norm_src[src[e]], 1.0f);
        atomicAdd(&g_norm_dst[d], 1.0f);
        atomicAdd(&g_row_off[d + 1], 1);
    }
}

// single-block exclusive scan over row_off (arr[i] = indeg[i-1], arr[0]=0)
__global__ void scan_kernel() {
    __shared__ int sh[1024];
    const int t = threadIdx.x;
    const int M = N_NODES + 1;
    const int chunk = (M + 1023) / 1024;
    const int s = t * chunk;
    const int e = min(s + chunk, M);
    int sum = 0;
    for (int i = s; i < e; i++) sum += g_row_off[i];
    sh[t] = sum;
    __syncthreads();
    for (int off = 1; off < 1024; off <<= 1) {
        int v = (t >= off) ? sh[t - off] : 0;
        __syncthreads();
        sh[t] += v;
        __syncthreads();
    }
    int run = (t == 0) ? 0 : sh[t - 1];
    for (int i = s; i < e; i++) {
        run += g_row_off[i];
        g_row_off[i] = run;            // row_off[n] = start offset of node n
        if (i < N_NODES) g_cursor[i] = run;
    }
}

__global__ void fill_kernel(const int* __restrict__ src, const int* __restrict__ dst) {
    int idx = blockIdx.x * blockDim.x + threadIdx.x;
    int stride = gridDim.x * blockDim.x;
    for (int e = idx; e < N_EDGES; e += stride) {
        int pos = atomicAdd(&g_cursor[dst[e]], 1);
        g_edge_src[pos] = src[e];
    }
}

__global__ void deg_finalize_kernel(const int* __restrict__ graph_ids) {
    int idx = blockIdx.x * blockDim.x + threadIdx.x;
    int stride = gridDim.x * blockDim.x;
    for (int i = idx; i < N_NODES; i += stride) {
        g_norm_src[i] = rsqrtf(fmaxf(g_norm_src[i], 1.0f));
        g_norm_dst[i] = rsqrtf(fmaxf(g_norm_dst[i], 1.0f));
        atomicAdd(&g_counts[graph_ids[i]], 1.0f);
    }
}

// ---------------- GEMM: C[M,NS] = diag(scale?) * A[M,146] @ W[146,146] (+bias) ----------------
// K-tiled (BK=73, 2 tiles), smem ~66KB -> 3 blocks/SM.
// 256 threads = 16x16, 4(row) x 10(col) micro-tile, BM=64 rows, all 160 cols.
#define GEMM_BM 64
#define GEMM_BK 73
#define GEMM_SMEM_FLOATS (GEMM_BK * 160 + GEMM_BK * 68)
#define GEMM_SMEM_BYTES  (GEMM_SMEM_FLOATS * 4)

__global__ void gemm_kernel(const float* __restrict__ Aext, int use_gh,
                            const float* __restrict__ W, const float* __restrict__ bias,
                            int use_scale, int out_hw)
{
    extern __shared__ float smem[];
    float* Ws = smem;                     // [73][160]
    float* At = smem + GEMM_BK * 160;     // [73][68] (transposed A tile)

    const float* A = use_gh ? g_h : Aext;
    const int lda = use_gh ? NS : DD;
    float* C = out_hw ? g_hW : g_h;
    const int tid = threadIdx.x;
    const int row0 = blockIdx.x * GEMM_BM;

    const int tx = tid & 15;
    const int ty = tid >> 4;
    float acc[4][10];
#pragma unroll
    for (int i = 0; i < 4; i++)
#pragma unroll
        for (int j = 0; j < 10; j++) acc[i][j] = 0.f;

    const float4* At4 = reinterpret_cast<const float4*>(At);
    const float2* Ws2 = reinterpret_cast<const float2*>(Ws);

    for (int t = 0; t < 2; t++) {
        const int k0 = t * GEMM_BK;
        // stage W tile (+ zero pad cols 146..159)
        for (int i = tid; i < GEMM_BK * 146; i += 256) {
            int k = i / 146, n = i - k * 146;
            Ws[k * 160 + n] = W[(k0 + k) * 146 + n];
        }
        for (int i = tid; i < GEMM_BK * 14; i += 256) {
            int k = i / 14, n = 146 + (i - k * 14);
            Ws[k * 160 + n] = 0.f;
        }
        // stage A tile transposed, apply row scale
        for (int i = tid; i < GEMM_BM * GEMM_BK; i += 256) {
            int r = i / GEMM_BK, kk = i - r * GEMM_BK;
            int row = row0 + r;
            float v = 0.f;
            if (row < N_NODES) {
                v = A[(size_t)row * lda + k0 + kk];
                if (use_scale) v *= g_norm_src[row];
            }
            At[kk * 68 + r] = v;
        }
        __syncthreads();

#pragma unroll 2
        for (int kk = 0; kk < GEMM_BK; kk++) {
            float4 a4 = At4[kk * 17 + ty];
            float av[4] = {a4.x, a4.y, a4.z, a4.w};
#pragma unroll
            for (int j = 0; j < 5; j++) {
                float2 w = Ws2[kk * 80 + tx * 5 + j];
#pragma unroll
                for (int i = 0; i < 4; i++) {
                    acc[i][2 * j]     += av[i] * w.x;
                    acc[i][2 * j + 1] += av[i] * w.y;
                }
            }
        }
        __syncthreads();
    }

#pragma unroll
    for (int i = 0; i < 4; i++) {
        int row = row0 + ty * 4 + i;
        if (row >= N_NODES) continue;
        float* crow = C + (size_t)row * NS;
#pragma unroll
        for (int jj = 0; jj < 10; jj++) {
            int col = tx * 10 + jj;
            float v = 0.f;
            if (col < DD) {
                v = acc[i][jj];
                if (bias) v += bias[col];
            }
            crow[col] = v;   // cols 146..159 get 0 -> pad stays clean
        }
    }
}

// ---------------- CSR gather (R7: flat loop, warp-uniform edge-id load, no shfl) ----------------
// Warp per node; lane owns float4 chunk `lane` (+ chunk 32+lane for lanes 0..7).
// Fuses finalize1: v = (sum * norm_dst + b) * snorm, writes g_agg, accumulates BN
// column sums in registers (8 atomics/lane at kernel end).
__global__ void gather_kernel(const float* __restrict__ snorm,
                              const float* __restrict__ bs, int layer)
{
    const int lane = threadIdx.x & 31;
    const int warp = (blockIdx.x * blockDim.x + threadIdx.x) >> 5;
    const int nwarps = (gridDim.x * blockDim.x) >> 5;

    // per-lane bias: chunk0 features lane*4..+3 (<128<DD); chunk1 (lane<8) 128+lane*4..+3
    float4 b0, b1 = make_float4(0.f, 0.f, 0.f, 0.f);
    {
        const float* bl = bs + layer * DD;
        int f = lane * 4;
        b0.x = __ldg(&bl[f + 0]); b0.y = __ldg(&bl[f + 1]);
        b0.z = __ldg(&bl[f + 2]); b0.w = __ldg(&bl[f + 3]);
        if (lane < 8) {
            int g = 128 + lane * 4;
            b1.x = (g + 0 < DD) ? __ldg(&bl[g + 0]) : 0.f;
            b1.y = (g + 1 < DD) ? __ldg(&bl[g + 1]) : 0.f;
            b1.z = (g + 2 < DD) ? __ldg(&bl[g + 2]) : 0.f;
            b1.w = (g + 3 < DD) ? __ldg(&bl[g + 3]) : 0.f;
        }
    }

    float4 s0 = make_float4(0.f,0.f,0.f,0.f), q0 = s0, s1 = s0, q1 = s0;

    for (int n = warp; n < N_NODES; n += nwarps) {
        const int beg = __ldg(&g_row_off[n]);
        const int end = __ldg(&g_row_off[n + 1]);
        float4 a0 = make_float4(0.f,0.f,0.f,0.f), a1 = a0;
#pragma unroll 2
        for (int e = beg; e < end; e++) {
            const int sidx = __ldg(&g_edge_src[e]);   // warp-uniform broadcast load
            const float4* row = reinterpret_cast<const float4*>(g_hW + (size_t)sidx * NS);
            float4 r0 = __ldg(&row[lane]);
            a0.x += r0.x; a0.y += r0.y; a0.z += r0.z; a0.w += r0.w;
            if (lane < 8) {
                float4 r1 = __ldg(&row[32 + lane]);
                a1.x += r1.x; a1.y += r1.y; a1.z += r1.z; a1.w += r1.w;
            }
        }
        const float nd = __ldg(&g_norm_dst[n]);
        const float sn = __ldg(&snorm[n]);
        float4 v0, v1;
        v0.x = (a0.x * nd + b0.x) * sn; v0.y = (a0.y * nd + b0.y) * sn;
        v0.z = (a0.z * nd + b0.z) * sn; v0.w = (a0.w * nd + b0.w) * sn;
        float4* outp = reinterpret_cast<float4*>(g_agg + (size_t)n * NS);
        outp[lane] = v0;
        s0.x += v0.x; s0.y += v0.y; s0.z += v0.z; s0.w += v0.w;
        q0.x += v0.x*v0.x; q0.y += v0.y*v0.y; q0.z += v0.z*v0.z; q0.w += v0.w*v0.w;
        if (lane < 8) {
            v1.x = (a1.x * nd + b1.x) * sn; v1.y = (a1.y * nd + b1.y) * sn;
            v1.z = (a1.z * nd + b1.z) * sn; v1.w = (a1.w * nd + b1.w) * sn;
            outp[32 + lane] = v1;
            s1.x += v1.x; s1.y += v1.y; s1.z += v1.z; s1.w += v1.w;
            q1.x += v1.x*v1.x; q1.y += v1.y*v1.y; q1.z += v1.z*v1.z; q1.w += v1.w*v1.w;
        }
    }

    {
        int f = lane * 4;
        atomicAdd(&g_bnsum[f + 0], s0.x); atomicAdd(&g_bnsum[f + 1], s0.y);
        atomicAdd(&g_bnsum[f + 2], s0.z); atomicAdd(&g_bnsum[f + 3], s0.w);
        atomicAdd(&g_bnsum[NS + f + 0], q0.x); atomicAdd(&g_bnsum[NS + f + 1], q0.y);
        atomicAdd(&g_bnsum[NS + f + 2], q0.z); atomicAdd(&g_bnsum[NS + f + 3], q0.w);
        if (lane < 8) {
            int g = 128 + lane * 4;
            atomicAdd(&g_bnsum[g + 0], s1.x); atomicAdd(&g_bnsum[g + 1], s1.y);
            atomicAdd(&g_bnsum[g + 2], s1.z); atomicAdd(&g_bnsum[g + 3], s1.w);
            atomicAdd(&g_bnsum[NS + g + 0], q1.x); atomicAdd(&g_bnsum[NS + g + 1], q1.y);
            atomicAdd(&g_bnsum[NS + g + 2], q1.z); atomicAdd(&g_bnsum[NS + g + 3], q1.w);
        }
    }
}

// ---------------- BN stats (+ self-zero bnsum for next layer) ----------------
__global__ void bn_stats_kernel() {
    const int f = threadIdx.x;   // blockDim = 160
    if (f < DD) {
        const float invN = 1.0f / (float)N_NODES;
        float mean = g_bnsum[f] * invN;
        float var = g_bnsum[NS + f] * invN - mean * mean;
        var = fmaxf(var, 0.f);
        g_mean[f] = mean;
        g_rstd[f] = rsqrtf(var + BN_EPS);
    }
    if (f < NS) { g_bnsum[f] = 0.f; g_bnsum[NS + f] = 0.f; }
}

// ---------------- finalize 2: h = h + relu(BN(agg)); hacc += h ----------------
__global__ void finalize2_kernel(const float* __restrict__ gammas,
                                 const float* __restrict__ betas, int layer)
{
    const int f = threadIdx.x;   // blockDim = 160
    const bool active = (f < DD);
    float mean = 0.f, rstd = 0.f, ga = 0.f, be = 0.f;
    if (active) {
        mean = g_mean[f];
        rstd = g_rstd[f];
        ga = __ldg(&gammas[layer * DD + f]);
        be = __ldg(&betas[layer * DD + f]);
    }
    const int per = (N_NODES + gridDim.x - 1) / gridDim.x;
    const int s = blockIdx.x * per;
    const int e = min(s + per, N_NODES);
#pragma unroll 4
    for (int node = s; node < e; node++) {
        if (active) {
            size_t idx = (size_t)node * NS + f;
            float bn = (g_agg[idx] - mean) * rstd * ga + be;
            float r = fmaxf(bn, 0.f);
            float hnew = g_h[idx] + r;
            g_h[idx] = hnew;
            g_hacc[idx] += hnew;
        }
    }
}

// ---------------- hg = segment_sum(hacc, graph_ids); sorted ids -> run-length flush ----------------
__global__ void hg_kernel(const int* __restrict__ graph_ids) {
    const int f = threadIdx.x;
    const bool active = (f < DD);
    const int per = (N_NODES + gridDim.x - 1) / gridDim.x;
    const int s = blockIdx.x * per;
    const int e = min(s + per, N_NODES);
    int cur = -1;
    float acc = 0.f;
    for (int node = s; node < e; node++) {
        int g = __ldg(&graph_ids[node]);
        if (g != cur) {
            if (cur >= 0 && active) atomicAdd(&g_hg[cur * DD + f], acc);
            cur = g;
            acc = 0.f;
        }
        if (active) acc += g_hacc[(size_t)node * NS + f];
    }
    if (cur >= 0 && active) atomicAdd(&g_hg[cur * DD + f], acc);
}

// ---------------- MLP readout: 146 -> 73 -> 36 -> 10, one block per graph ----------------
__global__ void readout_kernel(const float* __restrict__ W_r0, const float* __restrict__ b_r0,
                               const float* __restrict__ W_r1, const float* __restrict__ b_r1,
                               const float* __restrict__ W_r2, const float* __restrict__ b_r2,
                               float* __restrict__ out)
{
    __shared__ float sh[DD + 73 + 36];
    const int g = blockIdx.x;
    const int t = threadIdx.x;
    const float inv = 1.0f / fmaxf(g_counts[g], 1.0f);
    for (int k = t; k < DD; k += blockDim.x) sh[k] = g_hg[g * DD + k] * inv;
    __syncthreads();
    if (t < 73) {
        float a = b_r0[t];
        for (int k = 0; k < DD; k++) a += sh[k] * W_r0[k * 73 + t];
        sh[DD + t] = fmaxf(a, 0.f);
    }
    __syncthreads();
    if (t < 36) {
        float a = b_r1[t];
        for (int k = 0; k < 73; k++) a += sh[DD + k] * W_r1[k * 36 + t];
        sh[DD + 73 + t] = fmaxf(a, 0.f);
    }
    __syncthreads();
    if (t < 10) {
        float a = b_r2[t];
        for (int k = 0; k < 36; k++) a += sh[DD + 73 + k] * W_r2[k * 10 + t];
        out[g * 10 + t] = a;
    }
}

// ---------------- launch ----------------
extern "C" void kernel_launch(void* const* d_in, const int* in_sizes, int n_in,
                              void* d_out, int out_size)
{
    const float* nodes_feat = (const float*)d_in[0];
    const float* snorm      = (const float*)d_in[1];
    const float* W_emb      = (const float*)d_in[2];
    const float* b_emb      = (const float*)d_in[3];
    const float* Ws         = (const float*)d_in[4];
    const float* bs         = (const float*)d_in[5];
    const float* gammas     = (const float*)d_in[6];
    const float* betas      = (const float*)d_in[7];
    const float* W_r0       = (const float*)d_in[8];
    const float* b_r0       = (const float*)d_in[9];
    const float* W_r1       = (const float*)d_in[10];
    const float* b_r1       = (const float*)d_in[11];
    const float* W_r2       = (const float*)d_in[12];
    const float* b_r2       = (const float*)d_in[13];
    const int*   src        = (const int*)d_in[14];
    const int*   dst        = (const int*)d_in[15];
    const int*   gid        = (const int*)d_in[16];
    float* out = (float*)d_out;

    cudaFuncSetAttribute(gemm_kernel, cudaFuncAttributeMaxDynamicSharedMemorySize,
                         GEMM_SMEM_BYTES);

    const int gemm_blocks = (N_NODES + GEMM_BM - 1) / GEMM_BM;   // 782

    zero_init_kernel<<<1024, 256>>>();
    deg_kernel<<<(N_EDGES + 255) / 256, 256>>>(src, dst);
    scan_kernel<<<1, 1024>>>();
    fill_kernel<<<(N_EDGES + 255) / 256, 256>>>(src, dst);
    deg_finalize_kernel<<<(N_NODES + 255) / 256, 256>>>(gid);

    // embedding: h = nodes_feat @ W_emb + b_emb
    gemm_kernel<<<gemm_blocks, 256, GEMM_SMEM_BYTES>>>(nodes_feat, 0, W_emb, b_emb, 0, 0);

    for (int l = 0; l < 4; l++) {
        // hW = (h * norm_src) @ W_l
        gemm_kernel<<<gemm_blocks, 256, GEMM_SMEM_BYTES>>>(nullptr, 1, Ws + l * DD * DD,
                                                           nullptr, 1, 1);
        gather_kernel<<<1024, 256>>>(snorm, bs, l);
        bn_stats_kernel<<<1, 160>>>();
        finalize2_kernel<<<1024, 160>>>(gammas, betas, l);
    }

    hg_kernel<<<128, 160>>>(gid);
    readout_kernel<<<N_GRAPHS, 128>>>(W_r0, b_r0, W_r1, b_r1, W_r2, b_r2, out);
}

// round 8
// speedup vs baseline: 1.6692x; 1.6692x over previous
#include <cuda_runtime.h>
#include <cuda_bf16.h>

#define N_NODES 50000
#define N_EDGES 500000
#define N_GRAPHS 100
#define DD 146
#define NS 148          // padded row stride (float), 592B = 37 x float4
#define BN_EPS 1e-5f

// ---------------- scratch (static device globals; no allocation) ----------------
__device__ __align__(16) float g_h   [N_NODES * NS];
__device__ __align__(16) float g_hW  [N_NODES * NS];
__device__ __align__(16) float g_agg [N_NODES * NS];
__device__ __align__(16) float g_hacc[N_NODES * NS];
__device__ float g_norm_src[N_NODES];
__device__ float g_norm_dst[N_NODES];
__device__ float g_counts[N_GRAPHS];
__device__ __align__(16) float g_hg[N_GRAPHS * DD];
__device__ float g_bnsum[2 * NS];   // [0:NS) col sums, [NS:2NS) col sumsq
__device__ float g_mean[NS];
__device__ float g_rstd[NS];

// ---------------- helpers ----------------
__device__ __forceinline__ void red_add_v4(float4* p, float4 v) {
    asm volatile("red.global.add.v4.f32 [%0], {%1,%2,%3,%4};"
                 :: "l"(p), "f"(v.x), "f"(v.y), "f"(v.z), "f"(v.w) : "memory");
}

// ---------------- init / zero kernels ----------------
__global__ void zero_init_kernel() {
    int idx = blockIdx.x * blockDim.x + threadIdx.x;
    int stride = gridDim.x * blockDim.x;
    const float4 z4 = make_float4(0.f, 0.f, 0.f, 0.f);
    const int n4 = N_NODES * NS / 4;
    float4* hacc4 = reinterpret_cast<float4*>(g_hacc);
    for (int i = idx; i < n4; i += stride) hacc4[i] = z4;
    for (int i = idx; i < N_NODES; i += stride) { g_norm_src[i] = 0.f; g_norm_dst[i] = 0.f; }
    for (int i = idx; i < N_GRAPHS * DD; i += stride) g_hg[i] = 0.f;
    for (int i = idx; i < N_GRAPHS; i += stride) g_counts[i] = 0.f;
    for (int i = idx; i < 2 * NS; i += stride) g_bnsum[i] = 0.f;
}

__global__ void zero_agg_kernel() {
    int idx = blockIdx.x * blockDim.x + threadIdx.x;
    int stride = gridDim.x * blockDim.x;
    const float4 z4 = make_float4(0.f, 0.f, 0.f, 0.f);
    const int n4 = N_NODES * NS / 4;
    float4* agg4 = reinterpret_cast<float4*>(g_agg);
    for (int i = idx; i < n4; i += stride) agg4[i] = z4;
    for (int i = idx; i < 2 * NS; i += stride) g_bnsum[i] = 0.f;
}

// ---------------- degree norms + graph counts ----------------
__global__ void deg_kernel(const int* __restrict__ src, const int* __restrict__ dst) {
    int idx = blockIdx.x * blockDim.x + threadIdx.x;
    int stride = gridDim.x * blockDim.x;
    for (int e = idx; e < N_EDGES; e += stride) {
        atomicAdd(&g_norm_src[src[e]], 1.0f);
        atomicAdd(&g_norm_dst[dst[e]], 1.0f);
    }
}

__global__ void deg_finalize_kernel(const int* __restrict__ graph_ids) {
    int idx = blockIdx.x * blockDim.x + threadIdx.x;
    int stride = gridDim.x * blockDim.x;
    for (int i = idx; i < N_NODES; i += stride) {
        g_norm_src[i] = rsqrtf(fmaxf(g_norm_src[i], 1.0f));
        g_norm_dst[i] = rsqrtf(fmaxf(g_norm_dst[i], 1.0f));
        atomicAdd(&g_counts[graph_ids[i]], 1.0f);
    }
}

// ---------------- GEMM: C[M,NS] = diag(scale?) * A[M,146] @ W[146,146] (+bias) ----------------
// R8: K-tiled (BK=73, 2 tiles) -> smem 66KB -> 3 blocks/SM (vs 1 at 130KB in R5).
// 256 threads = 16x16, 4(row) x 10(col) micro-tile, BM=64 rows, all 148 cols.
#define GEMM_BM 64
#define GEMM_BK 73
#define GEMM_SMEM_FLOATS (GEMM_BK * 160 + GEMM_BK * 68)
#define GEMM_SMEM_BYTES  (GEMM_SMEM_FLOATS * 4)

__global__ void gemm_kernel(const float* __restrict__ Aext, int use_gh,
                            const float* __restrict__ W, const float* __restrict__ bias,
                            int use_scale, int out_hw)
{
    extern __shared__ float smem[];
    float* Ws = smem;                     // [73][160]
    float* At = smem + GEMM_BK * 160;     // [73][68] (transposed A tile)

    const float* A = use_gh ? g_h : Aext;
    const int lda = use_gh ? NS : DD;
    float* C = out_hw ? g_hW : g_h;
    const int tid = threadIdx.x;
    const int row0 = blockIdx.x * GEMM_BM;

    const int tx = tid & 15;
    const int ty = tid >> 4;
    float acc[4][10];
#pragma unroll
    for (int i = 0; i < 4; i++)
#pragma unroll
        for (int j = 0; j < 10; j++) acc[i][j] = 0.f;

    const float4* At4 = reinterpret_cast<const float4*>(At);
    const float2* Ws2 = reinterpret_cast<const float2*>(Ws);

    for (int t = 0; t < 2; t++) {
        const int k0 = t * GEMM_BK;
        // stage W tile (+ zero pad cols 146..159)
        for (int i = tid; i < GEMM_BK * 146; i += 256) {
            int k = i / 146, n = i - k * 146;
            Ws[k * 160 + n] = W[(k0 + k) * 146 + n];
        }
        for (int i = tid; i < GEMM_BK * 14; i += 256) {
            int k = i / 14, n = 146 + (i - k * 14);
            Ws[k * 160 + n] = 0.f;
        }
        // stage A tile transposed, apply row scale
        for (int i = tid; i < GEMM_BM * GEMM_BK; i += 256) {
            int r = i / GEMM_BK, kk = i - r * GEMM_BK;
            int row = row0 + r;
            float v = 0.f;
            if (row < N_NODES) {
                v = A[(size_t)row * lda + k0 + kk];
                if (use_scale) v *= g_norm_src[row];
            }
            At[kk * 68 + r] = v;
        }
        __syncthreads();

#pragma unroll 2
        for (int kk = 0; kk < GEMM_BK; kk++) {
            float4 a4 = At4[kk * 17 + ty];
            float av[4] = {a4.x, a4.y, a4.z, a4.w};
#pragma unroll
            for (int j = 0; j < 5; j++) {
                float2 w = Ws2[kk * 80 + tx * 5 + j];
#pragma unroll
                for (int i = 0; i < 4; i++) {
                    acc[i][2 * j]     += av[i] * w.x;
                    acc[i][2 * j + 1] += av[i] * w.y;
                }
            }
        }
        __syncthreads();
    }

#pragma unroll
    for (int i = 0; i < 4; i++) {
        int row = row0 + ty * 4 + i;
        if (row >= N_NODES) continue;
        float* crow = C + (size_t)row * NS;
#pragma unroll
        for (int jj = 0; jj < 10; jj++) {
            int col = tx * 10 + jj;
            if (col < NS) {
                float v = 0.f;
                if (col < DD) {
                    v = acc[i][jj];
                    if (bias) v += bias[col];
                }
                crow[col] = v;
            }
        }
    }
}

// ---------------- edge scatter: agg[dst] += hW[src], vectorized red.v4 ----------------
__global__ void scatter_kernel(const int* __restrict__ src, const int* __restrict__ dst) {
    const int warp_id = (blockIdx.x * blockDim.x + threadIdx.x) >> 5;
    const int lane = threadIdx.x & 31;
    if (warp_id >= N_EDGES) return;
    const int s = __ldg(&src[warp_id]);
    const int d = __ldg(&dst[warp_id]);
    const float4* srow = reinterpret_cast<const float4*>(g_hW + (size_t)s * NS);
    float4* drow = reinterpret_cast<float4*>(g_agg + (size_t)d * NS);
    float4 v = __ldg(&srow[lane]);
    red_add_v4(drow + lane, v);
    if (lane < 5) {
        float4 v2 = __ldg(&srow[32 + lane]);
        red_add_v4(drow + 32 + lane, v2);
    }
}

// ---------------- finalize 1: agg = (agg*norm_dst + b)*snorm (in place) + BN col sums ----------------
__global__ void finalize1_kernel(const float* __restrict__ snorm,
                                 const float* __restrict__ bs, int layer)
{
    const int f = threadIdx.x;   // blockDim = 160
    const bool active = (f < DD);
    const float b = active ? __ldg(&bs[layer * DD + f]) : 0.f;
    const int per = (N_NODES + gridDim.x - 1) / gridDim.x;
    const int s = blockIdx.x * per;
    const int e = min(s + per, N_NODES);
    float sum = 0.f, sumsq = 0.f;
#pragma unroll 4
    for (int node = s; node < e; node++) {
        float nd = __ldg(&g_norm_dst[node]);
        float sn = __ldg(&snorm[node]);
        if (active) {
            size_t idx = (size_t)node * NS + f;
            float v = (g_agg[idx] * nd + b) * sn;
            g_agg[idx] = v;
            sum += v;
            sumsq += v * v;
        }
    }
    if (active) {
        atomicAdd(&g_bnsum[f], sum);
        atomicAdd(&g_bnsum[NS + f], sumsq);
    }
}

__global__ void bn_stats_kernel() {
    const int f = threadIdx.x;
    if (f >= DD) return;
    const float invN = 1.0f / (float)N_NODES;
    float mean = g_bnsum[f] * invN;
    float var = g_bnsum[NS + f] * invN - mean * mean;
    var = fmaxf(var, 0.f);
    g_mean[f] = mean;
    g_rstd[f] = rsqrtf(var + BN_EPS);
}

// ---------------- finalize 2: h = h + relu(BN(agg)); hacc += h ----------------
__global__ void finalize2_kernel(const float* __restrict__ gammas,
                                 const float* __restrict__ betas, int layer)
{
    const int f = threadIdx.x;
    const bool active = (f < DD);
    float mean = 0.f, rstd = 0.f, ga = 0.f, be = 0.f;
    if (active) {
        mean = g_mean[f];
        rstd = g_rstd[f];
        ga = __ldg(&gammas[layer * DD + f]);
        be = __ldg(&betas[layer * DD + f]);
    }
    const int per = (N_NODES + gridDim.x - 1) / gridDim.x;
    const int s = blockIdx.x * per;
    const int e = min(s + per, N_NODES);
#pragma unroll 4
    for (int node = s; node < e; node++) {
        if (active) {
            size_t idx = (size_t)node * NS + f;
            float bn = (g_agg[idx] - mean) * rstd * ga + be;
            float r = fmaxf(bn, 0.f);
            float hnew = g_h[idx] + r;
            g_h[idx] = hnew;
            g_hacc[idx] += hnew;
        }
    }
}

// ---------------- hg = segment_sum(hacc, graph_ids); sorted ids -> run-length flush ----------------
__global__ void hg_kernel(const int* __restrict__ graph_ids) {
    const int f = threadIdx.x;
    const bool active = (f < DD);
    const int per = (N_NODES + gridDim.x - 1) / gridDim.x;
    const int s = blockIdx.x * per;
    const int e = min(s + per, N_NODES);
    int cur = -1;
    float acc = 0.f;
    for (int node = s; node < e; node++) {
        int g = __ldg(&graph_ids[node]);
        if (g != cur) {
            if (cur >= 0 && active) atomicAdd(&g_hg[cur * DD + f], acc);
            cur = g;
            acc = 0.f;
        }
        if (active) acc += g_hacc[(size_t)node * NS + f];
    }
    if (cur >= 0 && active) atomicAdd(&g_hg[cur * DD + f], acc);
}

// ---------------- MLP readout: 146 -> 73 -> 36 -> 10, one block per graph ----------------
__global__ void readout_kernel(const float* __restrict__ W_r0, const float* __restrict__ b_r0,
                               const float* __restrict__ W_r1, const float* __restrict__ b_r1,
                               const float* __restrict__ W_r2, const float* __restrict__ b_r2,
                               float* __restrict__ out)
{
    __shared__ float sh[DD + 73 + 36];
    const int g = blockIdx.x;
    const int t = threadIdx.x;
    const float inv = 1.0f / fmaxf(g_counts[g], 1.0f);
    for (int k = t; k < DD; k += blockDim.x) sh[k] = g_hg[g * DD + k] * inv;
    __syncthreads();
    if (t < 73) {
        float a = b_r0[t];
        for (int k = 0; k < DD; k++) a += sh[k] * W_r0[k * 73 + t];
        sh[DD + t] = fmaxf(a, 0.f);
    }
    __syncthreads();
    if (t < 36) {
        float a = b_r1[t];
        for (int k = 0; k < 73; k++) a += sh[DD + k] * W_r1[k * 36 + t];
        sh[DD + 73 + t] = fmaxf(a, 0.f);
    }
    __syncthreads();
    if (t < 10) {
        float a = b_r2[t];
        for (int k = 0; k < 36; k++) a += sh[DD + 73 + k] * W_r2[k * 10 + t];
        out[g * 10 + t] = a;
    }
}

// ---------------- launch ----------------
extern "C" void kernel_launch(void* const* d_in, const int* in_sizes, int n_in,
                              void* d_out, int out_size)
{
    const float* nodes_feat = (const float*)d_in[0];
    const float* snorm      = (const float*)d_in[1];
    const float* W_emb      = (const float*)d_in[2];
    const float* b_emb      = (const float*)d_in[3];
    const float* Ws         = (const float*)d_in[4];
    const float* bs         = (const float*)d_in[5];
    const float* gammas     = (const float*)d_in[6];
    const float* betas      = (const float*)d_in[7];
    const float* W_r0       = (const float*)d_in[8];
    const float* b_r0       = (const float*)d_in[9];
    const float* W_r1       = (const float*)d_in[10];
    const float* b_r1       = (const float*)d_in[11];
    const float* W_r2       = (const float*)d_in[12];
    const float* b_r2       = (const float*)d_in[13];
    const int*   src        = (const int*)d_in[14];
    const int*   dst        = (const int*)d_in[15];
    const int*   gid        = (const int*)d_in[16];
    float* out = (float*)d_out;

    cudaFuncSetAttribute(gemm_kernel, cudaFuncAttributeMaxDynamicSharedMemorySize,
                         GEMM_SMEM_BYTES);

    const int gemm_blocks = (N_NODES + GEMM_BM - 1) / GEMM_BM;        // 782
    const int scatter_blocks = (N_EDGES * 32) / 256;                   // 62500

    zero_init_kernel<<<1024, 256>>>();
    deg_kernel<<<(N_EDGES + 255) / 256, 256>>>(src, dst);
    deg_finalize_kernel<<<(N_NODES + 255) / 256, 256>>>(gid);

    // embedding: h = nodes_feat @ W_emb + b_emb
    gemm_kernel<<<gemm_blocks, 256, GEMM_SMEM_BYTES>>>(nodes_feat, 0, W_emb, b_emb, 0, 0);

    for (int l = 0; l < 4; l++) {
        // hW = (h * norm_src) @ W_l
        gemm_kernel<<<gemm_blocks, 256, GEMM_SMEM_BYTES>>>(nullptr, 1, Ws + l * DD * DD,
                                                           nullptr, 1, 1);
        zero_agg_kernel<<<1024, 256>>>();
        scatter_kernel<<<scatter_blocks, 256>>>(src, dst);
        finalize1_kernel<<<512, 160>>>(snorm, bs, l);
        bn_stats_kernel<<<1, 160>>>();
        finalize2_kernel<<<1024, 160>>>(gammas, betas, l);
    }

    hg_kernel<<<128, 160>>>(gid);
    readout_kernel<<<N_GRAPHS, 128>>>(W_r0, b_r0, W_r1, b_r1, W_r2, b_r2, out);
}